// round 13
// baseline (speedup 1.0000x reference)
#include <cuda_runtime.h>

// ExpandEvecs: out[b,k,n,m] = sum_{j<=k} ev[b,n,j] * ev[b,m,j]
// ev: [4,1,1024,16] fp32 ; out: [4,16,1024,1024] fp32 (256 MB)
// Wall time = 256MB / ~5.2 TB/s steady-state HBM write drain across ALL
// configs. This round: R7's best-measured structure (k-outer, 8-row tiles,
// 32KB contiguous bursts, grid 512, occ 2) with ONE delta: write-through
// stores (__stwt). WT streams data to DRAM as produced instead of building
// a dirty-L2 bulge that must drain between graph replays.

#define NDIM 1024
#define KDIM 16
#define TILE_N 8

__global__ __launch_bounds__(256, 2)
void expand_evecs_kernel(const float* __restrict__ ev, float* __restrict__ out) {
    const int b   = blockIdx.y;
    const int n0  = blockIdx.x * TILE_N;
    const int tid = threadIdx.x;
    const int m   = tid << 2;                 // 4 consecutive m-cols per thread

    __shared__ float a_s[TILE_N][KDIM];       // 8 x 16 a-rows for this n-tile

    const float* evb = ev + (size_t)b * NDIM * KDIM;

    // Load a-tile: 128 contiguous floats.
    if (tid < TILE_N * KDIM)
        a_s[tid >> 4][tid & 15] = evb[(size_t)n0 * KDIM + tid];

    // This thread's 4 B-rows, register-resident.
    float bw[4][KDIM];
    const float4* evb4 = (const float4*)evb;
    #pragma unroll
    for (int i = 0; i < 4; ++i) {
        #pragma unroll
        for (int q = 0; q < 4; ++q)
            ((float4*)bw[i])[q] = evb4[(size_t)(m + i) * (KDIM / 4) + q];
    }
    __syncthreads();

    // 8 running cumsum accumulators, one per n-row in the tile.
    float4 acc[TILE_N];
    #pragma unroll
    for (int nn = 0; nn < TILE_N; ++nn)
        acc[nn] = make_float4(0.f, 0.f, 0.f, 0.f);

    // Base pointer: plane k=0, row n0, col m.
    float* op = out + (((size_t)b * KDIM) * NDIM + n0) * NDIM + m;
    const size_t plane = (size_t)NDIM * NDIM;

    #pragma unroll
    for (int k = 0; k < KDIM; ++k) {
        // 8 consecutive 4KB rows of plane k -> 32KB contiguous CTA burst.
        #pragma unroll
        for (int nn = 0; nn < TILE_N; ++nn) {
            const float ak = a_s[nn][k];      // LDS broadcast
            acc[nn].x = fmaf(ak, bw[0][k], acc[nn].x);
            acc[nn].y = fmaf(ak, bw[1][k], acc[nn].y);
            acc[nn].z = fmaf(ak, bw[2][k], acc[nn].z);
            acc[nn].w = fmaf(ak, bw[3][k], acc[nn].w);
            __stwt((float4*)(op + (size_t)nn * NDIM), acc[nn]);   // write-through
        }
        op += plane;
    }
}

extern "C" void kernel_launch(void* const* d_in, const int* in_sizes, int n_in,
                              void* d_out, int out_size) {
    const float* ev = (const float*)d_in[0];
    float* out = (float*)d_out;
    const int B = in_sizes[0] / (NDIM * KDIM);   // = 4
    dim3 grid(NDIM / TILE_N, B);                 // 128 x 4 = 512 blocks
    expand_evecs_kernel<<<grid, 256>>>(ev, out);
}

// round 14
// speedup vs baseline: 1.0343x; 1.0343x over previous
#include <cuda_runtime.h>

// ExpandEvecs: out[b,k,n,m] = sum_{j<=k} ev[b,n,j] * ev[b,m,j]
// ev: [4,1,1024,16] fp32 ; out: [4,16,1024,1024] fp32 (256 MB)
// Wall time = 256MB / ~5.2 TB/s steady-state HBM write drain across ALL
// configs. This round: R7's best-measured structure (k-outer, 8-row tiles,
// 32KB contiguous bursts, grid 512, occ 2) with ONE delta: write-through
// stores (__stwt). WT streams data to DRAM as produced instead of building
// a dirty-L2 bulge that must drain between graph replays.

#define NDIM 1024
#define KDIM 16
#define TILE_N 8

__global__ __launch_bounds__(256, 2)
void expand_evecs_kernel(const float* __restrict__ ev, float* __restrict__ out) {
    const int b   = blockIdx.y;
    const int n0  = blockIdx.x * TILE_N;
    const int tid = threadIdx.x;
    const int m   = tid << 2;                 // 4 consecutive m-cols per thread

    __shared__ float a_s[TILE_N][KDIM];       // 8 x 16 a-rows for this n-tile

    const float* evb = ev + (size_t)b * NDIM * KDIM;

    // Load a-tile: 128 contiguous floats.
    if (tid < TILE_N * KDIM)
        a_s[tid >> 4][tid & 15] = evb[(size_t)n0 * KDIM + tid];

    // This thread's 4 B-rows, register-resident.
    float bw[4][KDIM];
    const float4* evb4 = (const float4*)evb;
    #pragma unroll
    for (int i = 0; i < 4; ++i) {
        #pragma unroll
        for (int q = 0; q < 4; ++q)
            ((float4*)bw[i])[q] = evb4[(size_t)(m + i) * (KDIM / 4) + q];
    }
    __syncthreads();

    // 8 running cumsum accumulators, one per n-row in the tile.
    float4 acc[TILE_N];
    #pragma unroll
    for (int nn = 0; nn < TILE_N; ++nn)
        acc[nn] = make_float4(0.f, 0.f, 0.f, 0.f);

    // Base pointer: plane k=0, row n0, col m.
    float* op = out + (((size_t)b * KDIM) * NDIM + n0) * NDIM + m;
    const size_t plane = (size_t)NDIM * NDIM;

    #pragma unroll
    for (int k = 0; k < KDIM; ++k) {
        // 8 consecutive 4KB rows of plane k -> 32KB contiguous CTA burst.
        #pragma unroll
        for (int nn = 0; nn < TILE_N; ++nn) {
            const float ak = a_s[nn][k];      // LDS broadcast
            acc[nn].x = fmaf(ak, bw[0][k], acc[nn].x);
            acc[nn].y = fmaf(ak, bw[1][k], acc[nn].y);
            acc[nn].z = fmaf(ak, bw[2][k], acc[nn].z);
            acc[nn].w = fmaf(ak, bw[3][k], acc[nn].w);
            __stwt((float4*)(op + (size_t)nn * NDIM), acc[nn]);   // write-through
        }
        op += plane;
    }
}

extern "C" void kernel_launch(void* const* d_in, const int* in_sizes, int n_in,
                              void* d_out, int out_size) {
    const float* ev = (const float*)d_in[0];
    float* out = (float*)d_out;
    const int B = in_sizes[0] / (NDIM * KDIM);   // = 4
    dim3 grid(NDIM / TILE_N, B);                 // 128 x 4 = 512 blocks
    expand_evecs_kernel<<<grid, 256>>>(ev, out);
}